// round 8
// baseline (speedup 1.0000x reference)
#include <cuda_runtime.h>
#include <cuda_bf16.h>

// LSTM: SEQ=512, BATCH=4096, INPUT=1, HIDDEN=100, OUTPUT=1
// lane = batch element (32-batch tile/CTA, 128 CTAs).
// 8 warps/CTA (2 per SMSP): warps 0-3 own 13 hidden units, warps 4-7 own 12
// (4*13 + 4*12 = 100, no padding). c-state in registers, h ping-pong in SMEM.
// Inner loop: fma.rn.f32x2 (2 fp32 MAC/instr), gates packed (i,f),(g,o),
// weights repacked once into SMEM as ulonglong2[(k, unit)].
// Model: FFMA2 floor 10.4K cyc/SMSP/step; LDS crossbar 11.2K wf/SM/step
// (binding). Predicted ~2.9-3.3 ms total.

#define T_SEQ 512
#define B_TOT 4096
#define H 100
#define TILE_B 32
#define NWARP 8

// SMEM layout (bytes):
//   Wp  : ulonglong2[H*H] = 160000  [k*H+u] -> ((w_i,w_f),(w_g,w_o))
//   bp  : ulonglong2[H]   = 1600
//   wih : ulonglong2[H]   = 1600
//   wl  : float[H]        = 400
//   hbuf: float[2][H][32] = 25600
#define OFF_WP    0
#define OFF_BP    160000
#define OFF_WIH   (OFF_BP + 16 * H)
#define OFF_WL    (OFF_WIH + 16 * H)
#define OFF_HBUF  (OFF_WL + 4 * H)
#define SMEM_BYTES (OFF_HBUF + 2 * H * TILE_B * 4)

typedef unsigned long long u64;

__device__ __forceinline__ u64 pack2(float lo, float hi) {
    u64 r;
    asm("mov.b64 %0, {%1, %2};" : "=l"(r)
        : "r"(__float_as_uint(lo)), "r"(__float_as_uint(hi)));
    return r;
}
__device__ __forceinline__ void unpack2(u64 v, float& lo, float& hi) {
    unsigned int a, b;
    asm("mov.b64 {%0, %1}, %2;" : "=r"(a), "=r"(b) : "l"(v));
    lo = __uint_as_float(a);
    hi = __uint_as_float(b);
}

#if __CUDACC_VER_MAJOR__ >= 13
// Packed 2-wide fp32 FMA (PTX 8.6+, 2x fp32 throughput on sm_103a)
__device__ __forceinline__ u64 ffma2(u64 a, u64 b, u64 c) {
    u64 d;
    asm("fma.rn.f32x2 %0, %1, %2, %3;" : "=l"(d) : "l"(a), "l"(b), "l"(c));
    return d;
}
#else
// Fallback: two scalar FMAs (correct, half throughput)
__device__ __forceinline__ u64 ffma2(u64 a, u64 b, u64 c) {
    float alo, ahi, blo, bhi, clo, chi;
    unpack2(a, alo, ahi);
    unpack2(b, blo, bhi);
    unpack2(c, clo, chi);
    return pack2(fmaf(alo, blo, clo), fmaf(ahi, bhi, chi));
}
#endif

__device__ __forceinline__ float sigf(float x) {
    return __fdividef(1.0f, 1.0f + __expf(-x));
}
__device__ __forceinline__ float tanhacc(float x) {
    // 2*sigmoid(2x)-1; saturates correctly at +/-1 for large |x|
    return __fdividef(2.0f, 1.0f + __expf(-2.0f * x)) - 1.0f;
}

// One full LSTM step for SUBU units starting at ubase.
template <int SUBU>
__device__ __forceinline__ void lstm_step(
    const ulonglong2* __restrict__ Wp,
    const ulonglong2* __restrict__ bp,
    const ulonglong2* __restrict__ wih,
    const float* __restrict__ hread,
    float* __restrict__ hwrite,
    u64 xp, float* c, int ubase, int lane)
{
    u64 acc0[SUBU], acc1[SUBU];  // (i,f) and (g,o) per unit
#pragma unroll
    for (int j = 0; j < SUBU; ++j) {
        ulonglong2 bb = bp[ubase + j];
        ulonglong2 wi = wih[ubase + j];
        acc0[j] = ffma2(xp, wi.x, bb.x);
        acc1[j] = ffma2(xp, wi.y, bb.y);
    }
#pragma unroll 2
    for (int k = 0; k < H; ++k) {
        const float hk = hread[k * TILE_B + lane];
        const u64 hp = pack2(hk, hk);
        const ulonglong2* __restrict__ wrow = Wp + k * H + ubase;
#pragma unroll
        for (int j = 0; j < SUBU; ++j) {
            ulonglong2 w = wrow[j];
            acc0[j] = ffma2(w.x, hp, acc0[j]);
            acc1[j] = ffma2(w.y, hp, acc1[j]);
        }
    }
#pragma unroll
    for (int j = 0; j < SUBU; ++j) {
        float gi, gf, gg, go;
        unpack2(acc0[j], gi, gf);
        unpack2(acc1[j], gg, go);
        float ig = sigf(gi);
        float fg = sigf(gf);
        float g  = tanhacc(gg);
        float og = sigf(go);
        float cn = fmaf(fg, c[j], ig * g);
        c[j] = cn;
        hwrite[(ubase + j) * TILE_B + lane] = og * tanhacc(cn);
    }
}

__global__ void __launch_bounds__(NWARP * 32, 1)
lstm_kernel(const float* __restrict__ X,      // [T, B]
            const float* __restrict__ W_ih,   // [4H, 1]
            const float* __restrict__ W_hh,   // [4H, H]
            const float* __restrict__ b_ih,   // [4H]
            const float* __restrict__ b_hh,   // [4H]
            const float* __restrict__ W_lin,  // [1, H]
            const float* __restrict__ b_lin,  // [1]
            float* __restrict__ out)          // [B, 1]
{
    extern __shared__ char smem[];
    ulonglong2* Wp  = (ulonglong2*)(smem + OFF_WP);
    ulonglong2* bp  = (ulonglong2*)(smem + OFF_BP);
    ulonglong2* wih = (ulonglong2*)(smem + OFF_WIH);
    float*      wl  = (float*)(smem + OFF_WL);
    float*      hb  = (float*)(smem + OFF_HBUF);

    const int tid  = threadIdx.x;
    const int lane = tid & 31;
    const int warp = tid >> 5;
    const int bglob = blockIdx.x * TILE_B + lane;
    // warps 0-3: 13 units at 13*warp; warps 4-7: 12 units at 52 + 12*(warp-4)
    const int ubase = (warp < 4) ? warp * 13 : 52 + (warp - 4) * 12;

    // ---- prologue: repack weights into SMEM (one-time, ~0.7% of runtime) ----
    for (int idx = tid; idx < H * H; idx += NWARP * 32) {
        int k = idx / H;
        int u = idx - k * H;
        ulonglong2 w;
        w.x = pack2(W_hh[(0 * H + u) * H + k], W_hh[(1 * H + u) * H + k]);
        w.y = pack2(W_hh[(2 * H + u) * H + k], W_hh[(3 * H + u) * H + k]);
        Wp[idx] = w;
    }
    for (int u = tid; u < H; u += NWARP * 32) {
        ulonglong2 bb, wi;
        bb.x = pack2(b_ih[0 * H + u] + b_hh[0 * H + u],
                     b_ih[1 * H + u] + b_hh[1 * H + u]);
        bb.y = pack2(b_ih[2 * H + u] + b_hh[2 * H + u],
                     b_ih[3 * H + u] + b_hh[3 * H + u]);
        bp[u] = bb;
        wi.x = pack2(W_ih[0 * H + u], W_ih[1 * H + u]);
        wi.y = pack2(W_ih[2 * H + u], W_ih[3 * H + u]);
        wih[u] = wi;
        wl[u] = W_lin[u];
    }
    for (int idx = tid; idx < H * TILE_B; idx += NWARP * 32)
        hb[idx] = 0.0f;
    __syncthreads();

    // ---- recurrence ----
    float c[13];
#pragma unroll
    for (int i = 0; i < 13; ++i) c[i] = 0.0f;

    int p = 0;
    float xcur = X[bglob];  // t = 0
    for (int t = 0; t < T_SEQ; ++t) {
        float xnext = (t + 1 < T_SEQ) ? X[(t + 1) * B_TOT + bglob] : 0.0f;
        const u64 xp = pack2(xcur, xcur);
        const float* __restrict__ hread = hb + p * (H * TILE_B);
        float* __restrict__ hwrite = hb + (p ^ 1) * (H * TILE_B);

        if (warp < 4)
            lstm_step<13>(Wp, bp, wih, hread, hwrite, xp, c, ubase, lane);
        else
            lstm_step<12>(Wp, bp, wih, hread, hwrite, xp, c, ubase, lane);

        __syncthreads();
        p ^= 1;
        xcur = xnext;
    }

    // ---- linear head (warp 0) ----
    if (warp == 0) {
        const float* hfin = hb + p * (H * TILE_B);
        float acc = b_lin[0];
#pragma unroll 4
        for (int k = 0; k < H; ++k)
            acc = fmaf(hfin[k * TILE_B + lane], wl[k], acc);
        out[bglob] = acc;
    }
}

extern "C" void kernel_launch(void* const* d_in, const int* in_sizes, int n_in,
                              void* d_out, int out_size) {
    const float* X     = (const float*)d_in[0];
    const float* W_ih  = (const float*)d_in[1];
    const float* W_hh  = (const float*)d_in[2];
    const float* b_ih  = (const float*)d_in[3];
    const float* b_hh  = (const float*)d_in[4];
    const float* W_lin = (const float*)d_in[5];
    const float* b_lin = (const float*)d_in[6];
    float* out = (float*)d_out;

    cudaFuncSetAttribute(lstm_kernel,
                         cudaFuncAttributeMaxDynamicSharedMemorySize,
                         SMEM_BYTES);
    lstm_kernel<<<B_TOT / TILE_B, NWARP * 32, SMEM_BYTES>>>(
        X, W_ih, W_hh, b_ih, b_hh, W_lin, b_lin, out);
}